// round 10
// baseline (speedup 1.0000x reference)
#include <cuda_runtime.h>
#include <math.h>

// Problem dims (fixed by the reference)
#define TT  512
#define BB  64
#define NIN 1024
#define HH  1024
#define GG  4096              // 4*HH
#define TBH (TT*BB*HH)
#define NCTA 128
#define NTHR 512
#define KSPLIT 8
#define KSLICE 128            // NIN / KSPLIT
#define NCOLS 256             // columns per CTA

typedef unsigned long long u64;

// Scratch (allocation-free rule: static __device__ globals)
__device__ float g_Zx[(size_t)TT*BB*GG];      // 512 MB: X@Wx + b
__device__ float g_P[KSPLIT*BB*GG];           // 8 MB: split-K partials
__device__ u64   g_bar;                       // grid barrier (monotonic)

// ---- packed f32x2 helpers ----
__device__ __forceinline__ u64 pack_dup(float x) {
    u64 r; unsigned xi = __float_as_uint(x);
    asm("mov.b64 %0, {%1, %1};" : "=l"(r) : "r"(xi));
    return r;
}
__device__ __forceinline__ void ffma2(u64& d, u64 a, u64 b) {
    asm("fma.rn.f32x2 %0, %1, %2, %0;" : "+l"(d) : "l"(a), "l"(b));
}
__device__ __forceinline__ float2 unpk(u64 v) {
    unsigned lo, hi;
    asm("mov.b64 {%0, %1}, %2;" : "=r"(lo), "=r"(hi) : "l"(v));
    return make_float2(__uint_as_float(lo), __uint_as_float(hi));
}

// ---- fast gate math (error ~1e-6 rel, budget is 1e-3) ----
__device__ __forceinline__ float sigm_f(float x) {
    return 1.f / (1.f + __expf(-x));
}
__device__ __forceinline__ float tanh_f(float x) {
    return 2.f / (1.f + __expf(-2.f * x)) - 1.f;
}

// ============================================================
// Kernel 1: Zx = X @ Wx + b  (M=32768, N=4096, K=1024) — validated
// ============================================================
__global__ __launch_bounds__(256)
void zx_gemm(const float* __restrict__ X, const float* __restrict__ W,
             const float* __restrict__ bias)
{
    __shared__ __align__(16) float As[8][128];
    __shared__ __align__(16) float Bs[8][128];
    const int tid  = threadIdx.x;
    const int brow = blockIdx.y * 128;
    const int bcol = blockIdx.x * 128;
    const int tx = tid & 15, ty = tid >> 4;

    const int a_row = tid >> 1;
    const int a_k   = (tid & 1) * 4;
    const int b_k   = tid >> 5;
    const int b_col = (tid & 31) * 4;

    const float* Ag = X + (size_t)(brow + a_row) * NIN + a_k;
    const float* Bg = W + (size_t)b_k * GG + bcol + b_col;

    float4 af = *(const float4*)Ag;
    float4 bf = *(const float4*)Bg;

    u64 acc[8][4];
    #pragma unroll
    for (int i = 0; i < 8; i++)
        #pragma unroll
        for (int j = 0; j < 4; j++) acc[i][j] = 0ull;

    for (int k0 = 0; k0 < NIN; k0 += 8) {
        As[a_k+0][a_row] = af.x; As[a_k+1][a_row] = af.y;
        As[a_k+2][a_row] = af.z; As[a_k+3][a_row] = af.w;
        *(float4*)&Bs[b_k][b_col] = bf;
        __syncthreads();
        if (k0 + 8 < NIN) {
            af = *(const float4*)(Ag + k0 + 8);
            bf = *(const float4*)(Bg + (size_t)(k0 + 8) * GG);
        }
        #pragma unroll
        for (int k = 0; k < 8; k++) {
            u64 bb[4];
            #pragma unroll
            for (int j = 0; j < 4; j++)
                bb[j] = *(const u64*)&Bs[k][tx*2 + j*32];
            #pragma unroll
            for (int i = 0; i < 8; i++) {
                u64 aa = pack_dup(As[k][ty*8 + i]);
                #pragma unroll
                for (int j = 0; j < 4; j++) ffma2(acc[i][j], aa, bb[j]);
            }
        }
        __syncthreads();
    }
    #pragma unroll
    for (int i = 0; i < 8; i++) {
        const size_t row = (size_t)(brow + ty*8 + i);
        #pragma unroll
        for (int j = 0; j < 4; j++) {
            const int col = bcol + tx*2 + j*32;
            float2 v = unpk(acc[i][j]);
            v.x += bias[col];
            v.y += bias[col + 1];
            *(float2*)&g_Zx[row * GG + col] = v;
        }
    }
}

// ============================================================
// Grid barrier: monotonic counter + nanosleep backoff.
// Relaxed polls + sleep keep the L2 line free so arrival atomics
// land immediately (round-9 version hammered the line with 127
// concurrent volatile-poll loops -> ~4us/barrier).
// ============================================================
__device__ __forceinline__ void grid_barrier()
{
    __syncthreads();
    if (threadIdx.x == 0) {
        __threadfence();                      // release prior STGs
        u64 my;
        asm volatile("atom.global.add.u64 %0, [%1], 1;"
                     : "=l"(my) : "l"(&g_bar) : "memory");
        const u64 target = (my / NCTA + 1ULL) * NCTA;
        while (true) {
            u64 v;
            asm volatile("ld.relaxed.gpu.global.u64 %0, [%1];"
                         : "=l"(v) : "l"(&g_bar) : "memory");
            if (v >= target) break;
            __nanosleep(64);
        }
        __threadfence();                      // acquire
    }
    __syncthreads();
}

// ============================================================
// Kernel 2: persistent LSTM recurrence.
// 128 CTAs x 512 threads. CTA (ks, cg): K-slice ks*128..+128,
// cols cg*256..+256. Per-thread 8 rows x 4 cols, col-paired f32x2
// accs. Wh slice (128 KB) + dup'd y (64 KB) persist in smem.
// Cell state c carried in a REGISTER (fixed cell per thread).
// ============================================================
__global__ __launch_bounds__(NTHR, 1)
void lstm_persist(const float* __restrict__ W,
                  const float* __restrict__ y0,
                  const float* __restrict__ c0,
                  const float* __restrict__ mask,
                  float* __restrict__ Y, float* __restrict__ C,
                  float* __restrict__ cT)
{
    extern __shared__ __align__(16) char smem[];
    float* Bs = (float*)smem;                       // [128][256] = 128 KB
    u64*   As = (u64*)(smem + KSLICE*NCOLS*4);      // [128][64] u64 = 64 KB

    const int tid = threadIdx.x;
    const int bx  = blockIdx.x;
    const int ks  = bx >> 4;            // 0..7   K-split
    const int cgb = (bx & 15) * NCOLS;  // column base in [0,4096)
    const int kb  = ks * KSLICE;        // K base within Wh

    // thread tile: rows ry*8..+7, cols cx*4..+3 (local)
    const int cx = tid & 63;            // 0..63 col-group (4 cols)
    const int ry = tid >> 6;            // 0..7  row-group (8 rows)

    // ---- one-time: Wh slice -> Bs [k][col], row-major, coalesced ----
    {
        const int c4 = (tid & 63) * 4;      // col 0..252
        const int kr = tid >> 6;            // 0..7
        for (int k = kr; k < KSLICE; k += 8) {
            *(float4*)&Bs[k*NCOLS + c4] =
                *(const float4*)&W[(size_t)(NIN + kb + k) * GG + cgb + c4];
        }
    }

    // A-fill assignment: row = tid&63, k-eighth = tid>>6 (16 k each)
    const int a_row = tid & 63;
    const int a_kq  = tid >> 6;          // 0..7 -> k = a_kq*16 .. +16
    __syncthreads();

    // Gate cell is FIXED per thread -> carry c in a register.
    const int cell  = bx*512 + tid;      // = b*1024 + h
    const int gb    = cell >> 10;        // batch
    const int gh    = cell & 1023;       // hidden index
    float c_reg = c0[cell];

    for (int t = 0; t < TT; t++) {
        const float* yp = (t == 0) ? y0 : (Y + (size_t)(t-1)*BB*HH);

        // ---- fill As[k][row] = (y,y) dup'd, transposed ----
        {
            const float* src = yp + (size_t)a_row*HH + kb + a_kq*16;
            #pragma unroll
            for (int j = 0; j < 4; j++) {
                float4 v = *(const float4*)(src + j*4);
                const int k0 = a_kq*16 + j*4;
                As[(k0+0)*64 + a_row] = pack_dup(v.x);
                As[(k0+1)*64 + a_row] = pack_dup(v.y);
                As[(k0+2)*64 + a_row] = pack_dup(v.z);
                As[(k0+3)*64 + a_row] = pack_dup(v.w);
            }
        }
        __syncthreads();

        // ---- GEMM: 8 rows x 2 col-pairs, K=128 ----
        u64 acc[8][2];
        #pragma unroll
        for (int i = 0; i < 8; i++) { acc[i][0] = 0ull; acc[i][1] = 0ull; }

        #pragma unroll 4
        for (int p = 0; p < KSLICE; p++) {
            ulonglong2 a01 = *(const ulonglong2*)&As[p*64 + ry*8 + 0];
            ulonglong2 a23 = *(const ulonglong2*)&As[p*64 + ry*8 + 2];
            ulonglong2 a45 = *(const ulonglong2*)&As[p*64 + ry*8 + 4];
            ulonglong2 a67 = *(const ulonglong2*)&As[p*64 + ry*8 + 6];
            ulonglong2 b01 = *(const ulonglong2*)&Bs[p*NCOLS + cx*4];
            u64 a[8] = {a01.x, a01.y, a23.x, a23.y, a45.x, a45.y, a67.x, a67.y};
            #pragma unroll
            for (int i = 0; i < 8; i++) {
                ffma2(acc[i][0], a[i], b01.x);
                ffma2(acc[i][1], a[i], b01.y);
            }
        }

        // ---- write K-split partials (col-paired accs ARE outputs) ----
        #pragma unroll
        for (int i = 0; i < 8; i++) {
            const int r = ry*8 + i;
            float2 v0 = unpk(acc[i][0]), v1 = unpk(acc[i][1]);
            *(float4*)&g_P[(size_t)(ks*BB + r)*GG + cgb + cx*4] =
                make_float4(v0.x, v0.y, v1.x, v1.y);
        }

        grid_barrier();   // all partials visible

        // ---- gates: 1 cell per thread, c carried in register ----
        {
            const float* zx = g_Zx + ((size_t)t*BB + gb)*GG + gh;
            float z[4];
            #pragma unroll
            for (int g = 0; g < 4; g++) {
                float s = zx[g*HH];
                #pragma unroll
                for (int kk = 0; kk < KSPLIT; kk++)
                    s += g_P[(size_t)(kk*BB + gb)*GG + g*HH + gh];
                z[g] = s;
            }
            const float ci = tanh_f(z[0]);
            const float ig = sigm_f(z[1]);
            const float fg = sigm_f(z[2]);
            const float og = sigm_f(z[3]);
            const float cp = c_reg;
            float c = ci*ig + cp*fg;
            float y = tanh_f(c)*og;
            const float m = mask[t*BB + gb];
            c = m*c + (1.f - m)*cp;
            y = m*y;
            c_reg = c;
            C[(size_t)t*BB*HH + cell] = c;
            Y[(size_t)t*BB*HH + cell] = y;
            if (t == TT-1) cT[cell] = c;
        }

        grid_barrier();   // Y[t] visible before next step's A fill
    }
}

// ============================================================
extern "C" void kernel_launch(void* const* d_in, const int* in_sizes, int n_in,
                              void* d_out, int out_size)
{
    const float* X    = (const float*)d_in[0];   // [512,64,1024]
    const float* W    = (const float*)d_in[1];   // [2048,4096]
    const float* bias = (const float*)d_in[2];   // [4096]
    const float* y0   = (const float*)d_in[3];   // [64,1024]
    const float* c0   = (const float*)d_in[4];   // [64,1024]
    const float* mask = (const float*)d_in[5];   // [512,64]

    float* out = (float*)d_out;
    float* Y  = out;                       // [512,64,1024]
    float* C  = out + (size_t)TBH;         // [512,64,1024]
    float* cT = out + 2 * (size_t)TBH;     // [64,1024]

    cudaFuncSetAttribute(lstm_persist,
                         cudaFuncAttributeMaxDynamicSharedMemorySize, 196608);

    // Node 1: input projection for all timesteps.
    zx_gemm<<<dim3(GG/128, (TT*BB)/128), 256>>>(X, W, bias);
    // Node 2: full recurrence in one persistent kernel.
    lstm_persist<<<NCTA, NTHR, 196608>>>(W, y0, c0, mask, Y, C, cT);
}

// round 12
// speedup vs baseline: 1.0334x; 1.0334x over previous
#include <cuda_runtime.h>
#include <math.h>

// Problem dims (fixed by the reference)
#define TT  512
#define BB  64
#define NIN 1024
#define HH  1024
#define GG  4096              // 4*HH
#define TBH (TT*BB*HH)
#define NCTA 128
#define NTHR 512
#define KSPLIT 8
#define KSLICE 128            // NIN / KSPLIT
#define NCOLS 256             // columns per CTA (gate-interleaved)

typedef unsigned long long u64;

// Scratch (allocation-free rule: static __device__ globals)
__device__ float g_Zx[(size_t)TT*BB*GG];        // 512 MB: X@Wx + b
__device__ float g_P[2*KSPLIT*BB*GG];           // 16 MB: split-K partials, x2 buffers
__device__ u64   g_c1[16*16];                   // per-col-group counters (128B stride)
__device__ u64   g_c2[8*16];                    // per-ks counters (128B stride)

// ---- packed f32x2 helpers ----
__device__ __forceinline__ u64 pack_dup(float x) {
    u64 r; unsigned xi = __float_as_uint(x);
    asm("mov.b64 %0, {%1, %1};" : "=l"(r) : "r"(xi));
    return r;
}
__device__ __forceinline__ void ffma2(u64& d, u64 a, u64 b) {
    asm("fma.rn.f32x2 %0, %1, %2, %0;" : "+l"(d) : "l"(a), "l"(b));
}
__device__ __forceinline__ float2 unpk(u64 v) {
    unsigned lo, hi;
    asm("mov.b64 {%0, %1}, %2;" : "=r"(lo), "=r"(hi) : "l"(v));
    return make_float2(__uint_as_float(lo), __uint_as_float(hi));
}
__device__ __forceinline__ u64 atom_add(u64* p) {
    u64 r;
    asm volatile("atom.global.add.u64 %0, [%1], 1;" : "=l"(r) : "l"(p) : "memory");
    return r;
}
__device__ __forceinline__ u64 ld_relaxed(const u64* p) {
    u64 r;
    asm volatile("ld.relaxed.gpu.global.u64 %0, [%1];" : "=l"(r) : "l"(p) : "memory");
    return r;
}
// ---- fast gate math (error ~1e-6 rel, budget is 1e-3) ----
__device__ __forceinline__ float sigm_f(float x) { return 1.f / (1.f + __expf(-x)); }
__device__ __forceinline__ float tanh_f(float x) { return 2.f / (1.f + __expf(-2.f*x)) - 1.f; }

// ============================================================
// Kernel 1: Zx = X @ Wx + b  (M=32768, N=4096, K=1024) — validated
// ============================================================
__global__ __launch_bounds__(256)
void zx_gemm(const float* __restrict__ X, const float* __restrict__ W,
             const float* __restrict__ bias)
{
    __shared__ __align__(16) float As[8][128];
    __shared__ __align__(16) float Bs[8][128];
    const int tid  = threadIdx.x;
    const int brow = blockIdx.y * 128;
    const int bcol = blockIdx.x * 128;
    const int tx = tid & 15, ty = tid >> 4;

    const int a_row = tid >> 1;
    const int a_k   = (tid & 1) * 4;
    const int b_k   = tid >> 5;
    const int b_col = (tid & 31) * 4;

    const float* Ag = X + (size_t)(brow + a_row) * NIN + a_k;
    const float* Bg = W + (size_t)b_k * GG + bcol + b_col;

    float4 af = *(const float4*)Ag;
    float4 bf = *(const float4*)Bg;

    u64 acc[8][4];
    #pragma unroll
    for (int i = 0; i < 8; i++)
        #pragma unroll
        for (int j = 0; j < 4; j++) acc[i][j] = 0ull;

    for (int k0 = 0; k0 < NIN; k0 += 8) {
        As[a_k+0][a_row] = af.x; As[a_k+1][a_row] = af.y;
        As[a_k+2][a_row] = af.z; As[a_k+3][a_row] = af.w;
        *(float4*)&Bs[b_k][b_col] = bf;
        __syncthreads();
        if (k0 + 8 < NIN) {
            af = *(const float4*)(Ag + k0 + 8);
            bf = *(const float4*)(Bg + (size_t)(k0 + 8) * GG);
        }
        #pragma unroll
        for (int k = 0; k < 8; k++) {
            u64 bb[4];
            #pragma unroll
            for (int j = 0; j < 4; j++)
                bb[j] = *(const u64*)&Bs[k][tx*2 + j*32];
            #pragma unroll
            for (int i = 0; i < 8; i++) {
                u64 aa = pack_dup(As[k][ty*8 + i]);
                #pragma unroll
                for (int j = 0; j < 4; j++) ffma2(acc[i][j], aa, bb[j]);
            }
        }
        __syncthreads();
    }
    #pragma unroll
    for (int i = 0; i < 8; i++) {
        const size_t row = (size_t)(brow + ty*8 + i);
        #pragma unroll
        for (int j = 0; j < 4; j++) {
            const int col = bcol + tx*2 + j*32;
            float2 v = unpk(acc[i][j]);
            v.x += bias[col];
            v.y += bias[col + 1];
            *(float2*)&g_Zx[row * GG + col] = v;
        }
    }
}

// ============================================================
// Kernel 2: persistent LSTM recurrence — scoped-barrier version.
// 128 CTAs x 512 threads. CTA (ks,cg): K-slice ks*128..+128,
// 256 gate-interleaved cols: local c <-> W col (c&3)*1024+cg*64+(c>>2).
// Sync: wait1 = 8-CTA group (same cg) partials-ready;
//       wait2 = 16-CTA group (Y cols for this ks) ready.
// g_P double-buffered on t parity. Zx prefetched during GEMM.
// ============================================================
__global__ __launch_bounds__(NTHR, 1)
void lstm_persist(const float* __restrict__ W,
                  const float* __restrict__ y0,
                  const float* __restrict__ c0,
                  const float* __restrict__ mask,
                  float* __restrict__ Y, float* __restrict__ C,
                  float* __restrict__ cT)
{
    extern __shared__ __align__(16) char smem[];
    float* Bs = (float*)smem;                       // [128][256] = 128 KB
    u64*   As = (u64*)(smem + KSLICE*NCOLS*4);      // [128][64] u64 = 64 KB

    const int tid = threadIdx.x;
    const int bx  = blockIdx.x;
    const int ks  = bx >> 4;            // 0..7   K-split
    const int cg  = bx & 15;            // 0..15  col-group
    const int kb  = ks * KSLICE;        // K base within Wh

    // GEMM thread tile: rows ry*8..+7, local cols cx*4..+3
    const int cx = tid & 63;
    const int ry = tid >> 6;

    // ---- one-time: Wh slice -> Bs, GATE-INTERLEAVED cols ----
    // idx = k*256 + g*64 + hl  ->  Bs[k*256 + hl*4 + g] = W[NIN+kb+k][g*1024+cg*64+hl]
    for (int idx = tid; idx < KSLICE*NCOLS; idx += NTHR) {
        const int k  = idx >> 8;
        const int g  = (idx >> 6) & 3;
        const int hl = idx & 63;
        Bs[k*NCOLS + hl*4 + g] =
            W[(size_t)(NIN + kb + k) * GG + g*HH + cg*64 + hl];
    }

    // A-fill assignment: row = tid&63, k-eighth = tid>>6 (16 k each)
    const int a_row = tid & 63;
    const int a_kq  = tid >> 6;
    __syncthreads();

    // Gate cell (fixed per thread): b = ks*8 + (tid>>6), h = cg*64 + (tid&63)
    const int gb   = ks*8 + (tid >> 6);
    const int ghl  = tid & 63;              // h - cg*64
    const int gh   = cg*64 + ghl;
    const int cell = gb*HH + gh;
    float c_reg = c0[cell];

    u64* ctr1 = &g_c1[cg*16];
    u64* ctr2w = &g_c2[(cg >> 1)*16];       // arrive here after gates
    u64* ctr2r = &g_c2[ks*16];              // wait here before A-fill
    u64 tk2 = 0;                            // ticket from last arrive2 (tid 0)

    for (int t = 0; t < TT; t++) {
        // ---- wait2: Y cols [ks*128, ks*128+128) ready (t>0) ----
        if (t > 0) {
            if (tid == 0) {
                const u64 target = (tk2/16 + 1) * 16;
                while (ld_relaxed(ctr2r) < target) __nanosleep(64);
                __threadfence();
            }
            __syncthreads();
        }
        const float* yp = (t == 0) ? y0 : (Y + (size_t)(t-1)*BB*HH);

        // ---- fill As[k][row] = (y,y) dup'd, transposed ----
        {
            const float* src = yp + (size_t)a_row*HH + kb + a_kq*16;
            #pragma unroll
            for (int j = 0; j < 4; j++) {
                float4 v = *(const float4*)(src + j*4);
                const int k0 = a_kq*16 + j*4;
                As[(k0+0)*64 + a_row] = pack_dup(v.x);
                As[(k0+1)*64 + a_row] = pack_dup(v.y);
                As[(k0+2)*64 + a_row] = pack_dup(v.z);
                As[(k0+3)*64 + a_row] = pack_dup(v.w);
            }
        }
        __syncthreads();

        // ---- GEMM: 8 rows x 2 col-pairs, K=128 (unchanged core) ----
        u64 acc[8][2];
        #pragma unroll
        for (int i = 0; i < 8; i++) { acc[i][0] = 0ull; acc[i][1] = 0ull; }

        #pragma unroll 4
        for (int p = 0; p < KSLICE; p++) {
            ulonglong2 a01 = *(const ulonglong2*)&As[p*64 + ry*8 + 0];
            ulonglong2 a23 = *(const ulonglong2*)&As[p*64 + ry*8 + 2];
            ulonglong2 a45 = *(const ulonglong2*)&As[p*64 + ry*8 + 4];
            ulonglong2 a67 = *(const ulonglong2*)&As[p*64 + ry*8 + 6];
            ulonglong2 b01 = *(const ulonglong2*)&Bs[p*NCOLS + cx*4];
            u64 a[8] = {a01.x, a01.y, a23.x, a23.y, a45.x, a45.y, a67.x, a67.y};
            #pragma unroll
            for (int i = 0; i < 8; i++) {
                ffma2(acc[i][0], a[i], b01.x);
                ffma2(acc[i][1], a[i], b01.y);
            }
        }

        // ---- prefetch Zx + mask for this thread's cell (DRAM, independent) ----
        float zx0, zx1, zx2, zx3, m;
        {
            const float* zx = g_Zx + ((size_t)t*BB + gb)*GG + gh;
            zx0 = zx[0*HH]; zx1 = zx[1*HH]; zx2 = zx[2*HH]; zx3 = zx[3*HH];
            m = mask[t*BB + gb];
        }

        // ---- write K-split partials to parity buffer ----
        float* Pbuf = g_P + (size_t)(t & 1) * KSPLIT*BB*GG;
        #pragma unroll
        for (int i = 0; i < 8; i++) {
            const int r = ry*8 + i;
            float2 v0 = unpk(acc[i][0]), v1 = unpk(acc[i][1]);
            *(float4*)&Pbuf[(size_t)(ks*BB + r)*GG + cg*NCOLS + cx*4] =
                make_float4(v0.x, v0.y, v1.x, v1.y);
        }

        // ---- wait1: all 8 ks-CTAs of group cg have written partials ----
        __syncthreads();
        if (tid == 0) {
            __threadfence();
            const u64 my = atom_add(ctr1);
            const u64 target = (my/8 + 1) * 8;
            while (ld_relaxed(ctr1) < target) __nanosleep(64);
            __threadfence();
        }
        __syncthreads();

        // ---- gates: 1 cell/thread; 4 gate-partials = 1 LDG.128 per ks ----
        {
            float z0 = zx0, z1 = zx1, z2 = zx2, z3 = zx3;
            #pragma unroll
            for (int kk = 0; kk < KSPLIT; kk++) {
                float4 p = *(const float4*)
                    &Pbuf[(size_t)(kk*BB + gb)*GG + cg*NCOLS + ghl*4];
                z0 += p.x; z1 += p.y; z2 += p.z; z3 += p.w;
            }
            const float ci = tanh_f(z0);
            const float ig = sigm_f(z1);
            const float fg = sigm_f(z2);
            const float og = sigm_f(z3);
            const float cp = c_reg;
            float c = ci*ig + cp*fg;
            float y = tanh_f(c)*og;
            c = m*c + (1.f - m)*cp;
            y = m*y;
            c_reg = c;
            C[(size_t)t*BB*HH + cell] = c;
            Y[(size_t)t*BB*HH + cell] = y;
            if (t == TT-1) cT[cell] = c;
        }

        // ---- arrive2: this CTA's Y cols (group cg>>1) are done ----
        __syncthreads();
        if (tid == 0) {
            __threadfence();
            tk2 = atom_add(ctr2w);
        }
    }
}

// ============================================================
extern "C" void kernel_launch(void* const* d_in, const int* in_sizes, int n_in,
                              void* d_out, int out_size)
{
    const float* X    = (const float*)d_in[0];   // [512,64,1024]
    const float* W    = (const float*)d_in[1];   // [2048,4096]
    const float* bias = (const float*)d_in[2];   // [4096]
    const float* y0   = (const float*)d_in[3];   // [64,1024]
    const float* c0   = (const float*)d_in[4];   // [64,1024]
    const float* mask = (const float*)d_in[5];   // [512,64]

    float* out = (float*)d_out;
    float* Y  = out;                       // [512,64,1024]
    float* C  = out + (size_t)TBH;         // [512,64,1024]
    float* cT = out + 2 * (size_t)TBH;     // [64,1024]

    cudaFuncSetAttribute(lstm_persist,
                         cudaFuncAttributeMaxDynamicSharedMemorySize, 196608);

    // Node 1: input projection for all timesteps.
    zx_gemm<<<dim3(GG/128, (TT*BB)/128), 256>>>(X, W, bias);
    // Node 2: full recurrence in one persistent kernel.
    lstm_persist<<<NCTA, NTHR, 196608>>>(W, y0, c0, mask, Y, C, cT);
}

// round 13
// speedup vs baseline: 1.1653x; 1.1277x over previous
#include <cuda_runtime.h>
#include <cuda_bf16.h>
#include <math.h>

// Problem dims (fixed by the reference)
#define TT  512
#define BB  64
#define NIN 1024
#define HH  1024
#define GG  4096              // 4*HH
#define TBH (TT*BB*HH)
#define NCTA 128
#define NTHR 512
#define KSPLIT 8
#define KSLICE 128            // NIN / KSPLIT
#define NCOLS 256             // columns per CTA (gate-interleaved)
#define KPX   (NIN/2)         // 512 k-pairs per row

typedef unsigned long long u64;
typedef unsigned int u32;

// Scratch (allocation-free rule: static __device__ globals)
__device__ float g_Zx[(size_t)TT*BB*GG];        // 512 MB: X@Wx + b
__device__ float g_P[2*KSPLIT*BB*GG];           // 16 MB: split-K partials, x2 buffers
__device__ u64   g_c1[16*16];                   // per-col-group counters
__device__ u64   g_c2[8*16];                    // per-ks counters
// bf16-split packed operands (k-pair u32): [row][kp]
__device__ u32 g_Xh[(size_t)TT*BB*KPX];         // 67 MB
__device__ u32 g_Xl[(size_t)TT*BB*KPX];         // 67 MB
__device__ u32 g_Wh[(size_t)GG*KPX];            // 8.4 MB  [n][kp]
__device__ u32 g_Wl[(size_t)GG*KPX];            // 8.4 MB

// ---- packed f32x2 helpers ----
__device__ __forceinline__ u64 pack_dup(float x) {
    u64 r; u32 xi = __float_as_uint(x);
    asm("mov.b64 %0, {%1, %1};" : "=l"(r) : "r"(xi));
    return r;
}
__device__ __forceinline__ void ffma2(u64& d, u64 a, u64 b) {
    asm("fma.rn.f32x2 %0, %1, %2, %0;" : "+l"(d) : "l"(a), "l"(b));
}
__device__ __forceinline__ float2 unpk(u64 v) {
    u32 lo, hi;
    asm("mov.b64 {%0, %1}, %2;" : "=r"(lo), "=r"(hi) : "l"(v));
    return make_float2(__uint_as_float(lo), __uint_as_float(hi));
}
__device__ __forceinline__ u64 atom_add(u64* p) {
    u64 r;
    asm volatile("atom.global.add.u64 %0, [%1], 1;" : "=l"(r) : "l"(p) : "memory");
    return r;
}
__device__ __forceinline__ u64 ld_relaxed(const u64* p) {
    u64 r;
    asm volatile("ld.relaxed.gpu.global.u64 %0, [%1];" : "=l"(r) : "l"(p) : "memory");
    return r;
}
__device__ __forceinline__ float sigm_f(float x) { return 1.f / (1.f + __expf(-x)); }
__device__ __forceinline__ float tanh_f(float x) { return 2.f / (1.f + __expf(-2.f*x)) - 1.f; }

// ---- bf16 split-pack helpers ----
__device__ __forceinline__ void split2(float a, float b, u32& hi, u32& lo) {
    __nv_bfloat16 ha = __float2bfloat16_rn(a);
    __nv_bfloat16 hb = __float2bfloat16_rn(b);
    __nv_bfloat16 la = __float2bfloat16_rn(a - __bfloat162float(ha));
    __nv_bfloat16 lb = __float2bfloat16_rn(b - __bfloat162float(hb));
    hi = (u32)__bfloat16_as_ushort(ha) | ((u32)__bfloat16_as_ushort(hb) << 16);
    lo = (u32)__bfloat16_as_ushort(la) | ((u32)__bfloat16_as_ushort(lb) << 16);
}

// ============================================================
// Preconvert: X -> Xh/Xl  (k-pair packed, [row][kp])
// ============================================================
__global__ __launch_bounds__(256)
void conv_x(const float* __restrict__ X)
{
    const size_t i = (size_t)blockIdx.x * 256 + threadIdx.x;   // pair index
    float2 v = ((const float2*)X)[i];
    u32 h, l; split2(v.x, v.y, h, l);
    g_Xh[i] = h; g_Xl[i] = l;
}

// ============================================================
// Preconvert: Wx -> Wh/Wl  ([n][kp] layout; reads coalesced in n)
// ============================================================
__global__ __launch_bounds__(256)
void conv_w(const float* __restrict__ W)
{
    const size_t i = (size_t)blockIdx.x * 256 + threadIdx.x;   // i = kp*GG + n
    const size_t kp = i / GG, n = i % GG;
    float a = W[(2*kp)    * GG + n];
    float b = W[(2*kp + 1)* GG + n];
    u32 h, l; split2(a, b, h, l);
    g_Wh[n*KPX + kp] = h;
    g_Wl[n*KPX + kp] = l;
}

// ============================================================
// Kernel 1: Zx = X @ Wx + b via bf16-split mma.sync (3 terms).
// CTA 128x128, 256 thr (8 warps x 64x32). K-chunk 16, double buffer.
// smem rows padded to stride 12 u32 -> operand LDS conflict-free.
// ============================================================
#define MMA_BF16(d, a0,a1,a2,a3, b0,b1) \
    asm volatile("mma.sync.aligned.m16n8k16.row.col.f32.bf16.bf16.f32 " \
        "{%0,%1,%2,%3}, {%4,%5,%6,%7}, {%8,%9}, {%0,%1,%2,%3};" \
        : "+f"(d[0]), "+f"(d[1]), "+f"(d[2]), "+f"(d[3]) \
        : "r"(a0), "r"(a1), "r"(a2), "r"(a3), "r"(b0), "r"(b1))

__global__ __launch_bounds__(256, 1)
void zx_mma(const float* __restrict__ bias)
{
    __shared__ u32 sm[2][4][128*12];     // [buf][Ah,Al,Bh,Bl][row*12+kp] 48 KB
    const int tid  = threadIdx.x;
    const int brow = blockIdx.y * 128;
    const int bcol = blockIdx.x * 128;
    const int lane = tid & 31;
    const int g    = lane >> 2;
    const int tig  = lane & 3;
    const int w    = tid >> 5;
    const int warpRow = (w >> 2) * 64;   // local
    const int warpCol = (w & 3) * 32;    // local

    // staging: thread -> (row srow, 4 k-pairs at sq)
    const int srow = tid >> 1;
    const int sq   = (tid & 1) * 4;
    const size_t aoff = (size_t)(brow + srow) * KPX + sq;
    const size_t boff = (size_t)(bcol + srow) * KPX + sq;

    float acc[4][4][4];
    #pragma unroll
    for (int mi = 0; mi < 4; mi++)
        #pragma unroll
        for (int ni = 0; ni < 4; ni++)
            #pragma unroll
            for (int q = 0; q < 4; q++) acc[mi][ni][q] = 0.f;

    // prologue: stage chunk 0
    {
        uint4 rah = *(const uint4*)&g_Xh[aoff];
        uint4 ral = *(const uint4*)&g_Xl[aoff];
        uint4 rbh = *(const uint4*)&g_Wh[boff];
        uint4 rbl = *(const uint4*)&g_Wl[boff];
        *(uint4*)&sm[0][0][srow*12 + sq] = rah;
        *(uint4*)&sm[0][1][srow*12 + sq] = ral;
        *(uint4*)&sm[0][2][srow*12 + sq] = rbh;
        *(uint4*)&sm[0][3][srow*12 + sq] = rbl;
    }
    __syncthreads();

    for (int kc = 0; kc < NIN/16; kc++) {
        const int buf = kc & 1;
        uint4 rah, ral, rbh, rbl;
        if (kc + 1 < NIN/16) {
            const size_t ka = aoff + (size_t)(kc+1)*8;
            const size_t kb = boff + (size_t)(kc+1)*8;
            rah = *(const uint4*)&g_Xh[ka];
            ral = *(const uint4*)&g_Xl[ka];
            rbh = *(const uint4*)&g_Wh[kb];
            rbl = *(const uint4*)&g_Wl[kb];
        }

        // ---- compute from sm[buf] ----
        const u32* Ah = sm[buf][0];
        const u32* Al = sm[buf][1];
        const u32* Bh = sm[buf][2];
        const u32* Bl = sm[buf][3];

        u32 bh[4][2], bl[4][2];
        #pragma unroll
        for (int ni = 0; ni < 4; ni++) {
            const int nb = (warpCol + ni*8 + g) * 12;
            bh[ni][0] = Bh[nb + tig];     bh[ni][1] = Bh[nb + tig + 4];
            bl[ni][0] = Bl[nb + tig];     bl[ni][1] = Bl[nb + tig + 4];
        }
        #pragma unroll
        for (int mi = 0; mi < 4; mi++) {
            const int ra = (warpRow + mi*16 + g) * 12;
            const int rb = ra + 8*12;
            u32 ah0 = Ah[ra + tig],     ah1 = Ah[rb + tig];
            u32 ah2 = Ah[ra + tig + 4], ah3 = Ah[rb + tig + 4];
            u32 al0 = Al[ra + tig],     al1 = Al[rb + tig];
            u32 al2 = Al[ra + tig + 4], al3 = Al[rb + tig + 4];
            #pragma unroll
            for (int ni = 0; ni < 4; ni++) {
                MMA_BF16(acc[mi][ni], ah0, ah1, ah2, ah3, bh[ni][0], bh[ni][1]);
                MMA_BF16(acc[mi][ni], ah0, ah1, ah2, ah3, bl[ni][0], bl[ni][1]);
                MMA_BF16(acc[mi][ni], al0, al1, al2, al3, bh[ni][0], bh[ni][1]);
            }
        }

        if (kc + 1 < NIN/16) {
            __syncthreads();
            const int nb = buf ^ 1;
            *(uint4*)&sm[nb][0][srow*12 + sq] = rah;
            *(uint4*)&sm[nb][1][srow*12 + sq] = ral;
            *(uint4*)&sm[nb][2][srow*12 + sq] = rbh;
            *(uint4*)&sm[nb][3][srow*12 + sq] = rbl;
            __syncthreads();
        }
    }

    // ---- epilogue: bias + store f32 ----
    #pragma unroll
    for (int mi = 0; mi < 4; mi++) {
        const int row0 = brow + warpRow + mi*16 + g;
        #pragma unroll
        for (int ni = 0; ni < 4; ni++) {
            const int col = bcol + warpCol + ni*8 + tig*2;
            const float2 b2 = *(const float2*)&bias[col];
            float2 v0 = make_float2(acc[mi][ni][0] + b2.x, acc[mi][ni][1] + b2.y);
            float2 v1 = make_float2(acc[mi][ni][2] + b2.x, acc[mi][ni][3] + b2.y);
            *(float2*)&g_Zx[(size_t)row0 * GG + col]       = v0;
            *(float2*)&g_Zx[(size_t)(row0+8) * GG + col]   = v1;
        }
    }
}

// ============================================================
// Kernel 2: persistent LSTM recurrence — UNCHANGED from validated
// round-12 version (scoped barriers, gate-interleaved B, parity g_P).
// ============================================================
__global__ __launch_bounds__(NTHR, 1)
void lstm_persist(const float* __restrict__ W,
                  const float* __restrict__ y0,
                  const float* __restrict__ c0,
                  const float* __restrict__ mask,
                  float* __restrict__ Y, float* __restrict__ C,
                  float* __restrict__ cT)
{
    extern __shared__ __align__(16) char smem[];
    float* Bs = (float*)smem;                       // [128][256] = 128 KB
    u64*   As = (u64*)(smem + KSLICE*NCOLS*4);      // [128][64] u64 = 64 KB

    const int tid = threadIdx.x;
    const int bx  = blockIdx.x;
    const int ks  = bx >> 4;
    const int cg  = bx & 15;
    const int kb  = ks * KSLICE;

    const int cx = tid & 63;
    const int ry = tid >> 6;

    for (int idx = tid; idx < KSLICE*NCOLS; idx += NTHR) {
        const int k  = idx >> 8;
        const int g  = (idx >> 6) & 3;
        const int hl = idx & 63;
        Bs[k*NCOLS + hl*4 + g] =
            W[(size_t)(NIN + kb + k) * GG + g*HH + cg*64 + hl];
    }

    const int a_row = tid & 63;
    const int a_kq  = tid >> 6;
    __syncthreads();

    const int gb   = ks*8 + (tid >> 6);
    const int ghl  = tid & 63;
    const int gh   = cg*64 + ghl;
    const int cell = gb*HH + gh;
    float c_reg = c0[cell];

    u64* ctr1  = &g_c1[cg*16];
    u64* ctr2w = &g_c2[(cg >> 1)*16];
    u64* ctr2r = &g_c2[ks*16];
    u64 tk2 = 0;

    for (int t = 0; t < TT; t++) {
        if (t > 0) {
            if (tid == 0) {
                const u64 target = (tk2/16 + 1) * 16;
                while (ld_relaxed(ctr2r) < target) __nanosleep(64);
                __threadfence();
            }
            __syncthreads();
        }
        const float* yp = (t == 0) ? y0 : (Y + (size_t)(t-1)*BB*HH);

        {
            const float* src = yp + (size_t)a_row*HH + kb + a_kq*16;
            #pragma unroll
            for (int j = 0; j < 4; j++) {
                float4 v = *(const float4*)(src + j*4);
                const int k0 = a_kq*16 + j*4;
                As[(k0+0)*64 + a_row] = pack_dup(v.x);
                As[(k0+1)*64 + a_row] = pack_dup(v.y);
                As[(k0+2)*64 + a_row] = pack_dup(v.z);
                As[(k0+3)*64 + a_row] = pack_dup(v.w);
            }
        }
        __syncthreads();

        u64 acc[8][2];
        #pragma unroll
        for (int i = 0; i < 8; i++) { acc[i][0] = 0ull; acc[i][1] = 0ull; }

        #pragma unroll 4
        for (int p = 0; p < KSLICE; p++) {
            ulonglong2 a01 = *(const ulonglong2*)&As[p*64 + ry*8 + 0];
            ulonglong2 a23 = *(const ulonglong2*)&As[p*64 + ry*8 + 2];
            ulonglong2 a45 = *(const ulonglong2*)&As[p*64 + ry*8 + 4];
            ulonglong2 a67 = *(const ulonglong2*)&As[p*64 + ry*8 + 6];
            ulonglong2 b01 = *(const ulonglong2*)&Bs[p*NCOLS + cx*4];
            u64 a[8] = {a01.x, a01.y, a23.x, a23.y, a45.x, a45.y, a67.x, a67.y};
            #pragma unroll
            for (int i = 0; i < 8; i++) {
                ffma2(acc[i][0], a[i], b01.x);
                ffma2(acc[i][1], a[i], b01.y);
            }
        }

        float zx0, zx1, zx2, zx3, m;
        {
            const float* zx = g_Zx + ((size_t)t*BB + gb)*GG + gh;
            zx0 = zx[0*HH]; zx1 = zx[1*HH]; zx2 = zx[2*HH]; zx3 = zx[3*HH];
            m = mask[t*BB + gb];
        }

        float* Pbuf = g_P + (size_t)(t & 1) * KSPLIT*BB*GG;
        #pragma unroll
        for (int i = 0; i < 8; i++) {
            const int r = ry*8 + i;
            float2 v0 = unpk(acc[i][0]), v1 = unpk(acc[i][1]);
            *(float4*)&Pbuf[(size_t)(ks*BB + r)*GG + cg*NCOLS + cx*4] =
                make_float4(v0.x, v0.y, v1.x, v1.y);
        }

        __syncthreads();
        if (tid == 0) {
            __threadfence();
            const u64 my = atom_add(ctr1);
            const u64 target = (my/8 + 1) * 8;
            while (ld_relaxed(ctr1) < target) __nanosleep(64);
            __threadfence();
        }
        __syncthreads();

        {
            float z0 = zx0, z1 = zx1, z2 = zx2, z3 = zx3;
            #pragma unroll
            for (int kk = 0; kk < KSPLIT; kk++) {
                float4 p = *(const float4*)
                    &Pbuf[(size_t)(kk*BB + gb)*GG + cg*NCOLS + ghl*4];
                z0 += p.x; z1 += p.y; z2 += p.z; z3 += p.w;
            }
            const float ci = tanh_f(z0);
            const float ig = sigm_f(z1);
            const float fg = sigm_f(z2);
            const float og = sigm_f(z3);
            const float cp = c_reg;
            float c = ci*ig + cp*fg;
            float y = tanh_f(c)*og;
            c = m*c + (1.f - m)*cp;
            y = m*y;
            c_reg = c;
            C[(size_t)t*BB*HH + cell] = c;
            Y[(size_t)t*BB*HH + cell] = y;
            if (t == TT-1) cT[cell] = c;
        }

        __syncthreads();
        if (tid == 0) {
            __threadfence();
            tk2 = atom_add(ctr2w);
        }
    }
}

// ============================================================
extern "C" void kernel_launch(void* const* d_in, const int* in_sizes, int n_in,
                              void* d_out, int out_size)
{
    const float* X    = (const float*)d_in[0];   // [512,64,1024]
    const float* W    = (const float*)d_in[1];   // [2048,4096]
    const float* bias = (const float*)d_in[2];   // [4096]
    const float* y0   = (const float*)d_in[3];   // [64,1024]
    const float* c0   = (const float*)d_in[4];   // [64,1024]
    const float* mask = (const float*)d_in[5];   // [512,64]

    float* out = (float*)d_out;
    float* Y  = out;                       // [512,64,1024]
    float* C  = out + (size_t)TBH;         // [512,64,1024]
    float* cT = out + 2 * (size_t)TBH;     // [64,1024]

    cudaFuncSetAttribute(lstm_persist,
                         cudaFuncAttributeMaxDynamicSharedMemorySize, 196608);

    // Node 1-2: bf16-split preconversion of X and Wx.
    conv_x<<<(TT*BB*NIN/2)/256, 256>>>(X);
    conv_w<<<(GG*KPX)/256, 256>>>(W);
    // Node 3: input projection via tensor cores.
    zx_mma<<<dim3(GG/128, (TT*BB)/128), 256>>>(bias);
    // Node 4: full recurrence in one persistent kernel.
    lstm_persist<<<NCTA, NTHR, 196608>>>(W, y0, c0, mask, Y, C, cT);
}